// round 1
// baseline (speedup 1.0000x reference)
#include <cuda_runtime.h>
#include <cuda_bf16.h>

// ConvModLayer: out[b,o] = c * siginv[b,o] * conv2d(x[b]*s[b], W)[o]
// c = 1/sqrt(512*9); siginv[b,o] = rsqrt(c^2 * sum_i s[b,i]^2 * wsq[o,i] + 1e-8)

#define B  16
#define C  512
#define O  512
#define H  64
#define W  64
#define KK 9

#define TH 8     // output rows per CTA
#define TW 32    // output cols per CTA
#define OT 32    // output channels per CTA
#define ICB 2    // input channels per mainloop step

#define XSTRIDE 35   // padded smem row stride (35 mod 32 = 3 -> conflict-free)

__device__ float g_wsq[O * C];        // sum over taps of W^2
__device__ float g_siginv[B * O];     // demodulation factor

// ---------------------------------------------------------------------------
// Kernel 1: wsq[o,i] = sum_t W[o,i,t]^2
// ---------------------------------------------------------------------------
__global__ void wsq_kernel(const float* __restrict__ w) {
    int idx = blockIdx.x * blockDim.x + threadIdx.x;   // o*512 + i
    if (idx >= O * C) return;
    const float* p = w + (long)idx * KK;
    float sum = 0.f;
#pragma unroll
    for (int t = 0; t < KK; t++) {
        float v = p[t];
        sum += v * v;
    }
    g_wsq[idx] = sum;
}

// ---------------------------------------------------------------------------
// Kernel 2: siginv[b,o] = rsqrt(c^2 * sum_i s[b,i]^2 * wsq[o,i] + 1e-8)
// one warp per (b,o)
// ---------------------------------------------------------------------------
__global__ void siginv_kernel(const float* __restrict__ s) {
    int gw = blockIdx.x * (blockDim.x >> 5) + (threadIdx.x >> 5); // b*512 + o
    if (gw >= B * O) return;
    int b = gw >> 9;
    int o = gw & 511;
    int lane = threadIdx.x & 31;

    float sum = 0.f;
    for (int i = lane; i < C; i += 32) {
        float sv = s[b * C + i];
        sum += sv * sv * g_wsq[o * C + i];
    }
#pragma unroll
    for (int off = 16; off > 0; off >>= 1)
        sum += __shfl_xor_sync(0xFFFFFFFFu, sum, off);

    if (lane == 0) {
        const float c2 = 1.0f / (float)(C * KK);   // (1/sqrt(4608))^2
        g_siginv[gw] = rsqrtf(sum * c2 + 1e-8f);
    }
}

// ---------------------------------------------------------------------------
// Kernel 3: the conv mainloop.
// Grid: (16 spatial tiles, 16 o-tiles, 16 batches). Block: 256 threads.
// Thread t: og = t>>6 (o-group of 8), p = t&63, r = p>>3 (row), cg = p&7
// -> computes 8 output channels x 4 consecutive cols at row h0+r.
// ---------------------------------------------------------------------------
__global__ void __launch_bounds__(256)
conv_kernel(const float* __restrict__ x, const float* __restrict__ s,
            const float* __restrict__ w, float* __restrict__ out) {
    const int b  = blockIdx.z;
    const int ob = blockIdx.y;                 // o tile: channels ob*32 ..
    const int sp = blockIdx.x;
    const int h0 = (sp >> 1) * TH;
    const int w0 = (sp & 1) * TW;

    const int tid = threadIdx.x;
    const int og  = tid >> 6;                  // 0..3
    const int p   = tid & 63;
    const int r   = p >> 3;                    // 0..7
    const int cg  = p & 7;                     // 0..7 -> cols cg*4..cg*4+3

    __shared__ float sx[ICB][(TH + 2) * XSTRIDE];   // 10 rows x 35
    __shared__ float sw[ICB][OT * KK];              // [o][tap]

    float acc[8][4];
#pragma unroll
    for (int j = 0; j < 8; j++)
#pragma unroll
        for (int q = 0; q < 4; q++) acc[j][q] = 0.f;

    const int colbase = cg * 4;

    for (int ic0 = 0; ic0 < C; ic0 += ICB) {
        // ---- load x halo (with s-modulation folded in) ----
#pragma unroll
        for (int idx = tid; idx < ICB * (TH + 2) * (TW + 2); idx += 256) {
            int ch  = idx / ((TH + 2) * (TW + 2));
            int rem = idx - ch * ((TH + 2) * (TW + 2));
            int hh  = rem / (TW + 2);
            int ww  = rem - hh * (TW + 2);
            int gh  = h0 - 1 + hh;
            int gw  = w0 - 1 + ww;
            int ic  = ic0 + ch;
            float v = 0.f;
            if (gh >= 0 && gh < H && gw >= 0 && gw < W)
                v = x[(((long)b * C + ic) * H + gh) * W + gw] * __ldg(&s[b * C + ic]);
            sx[ch][hh * XSTRIDE + ww] = v;
        }
        // ---- load weight slab ----
#pragma unroll
        for (int idx = tid; idx < ICB * OT * KK; idx += 256) {
            int ch  = idx / (OT * KK);
            int rem = idx - ch * (OT * KK);
            int oo  = rem / KK;
            int t   = rem - oo * KK;
            sw[ch][oo * KK + t] =
                w[(((long)(ob * OT + oo)) * C + (ic0 + ch)) * KK + t];
        }
        __syncthreads();

        // ---- compute ----
#pragma unroll
        for (int ch = 0; ch < ICB; ch++) {
            float xv[3][6];
#pragma unroll
            for (int dh = 0; dh < 3; dh++)
#pragma unroll
                for (int j = 0; j < 6; j++)
                    xv[dh][j] = sx[ch][(r + dh) * XSTRIDE + colbase + j];

#pragma unroll
            for (int j = 0; j < 8; j++) {
                const float* wp = &sw[ch][(og * 8 + j) * KK];
                float wv[9];
#pragma unroll
                for (int t = 0; t < 9; t++) wv[t] = wp[t];
#pragma unroll
                for (int dh = 0; dh < 3; dh++)
#pragma unroll
                    for (int dw = 0; dw < 3; dw++)
#pragma unroll
                        for (int q = 0; q < 4; q++)
                            acc[j][q] += wv[dh * 3 + dw] * xv[dh][q + dw];
            }
        }
        __syncthreads();
    }

    // ---- epilogue: scale by c * siginv and store ----
    const float cc = rsqrtf((float)(C * KK));   // 1/sqrt(4608)
#pragma unroll
    for (int j = 0; j < 8; j++) {
        int o = ob * OT + og * 8 + j;
        float scale = cc * g_siginv[b * O + o];
        float4 v;
        v.x = acc[j][0] * scale;
        v.y = acc[j][1] * scale;
        v.z = acc[j][2] * scale;
        v.w = acc[j][3] * scale;
        *reinterpret_cast<float4*>(
            &out[(((long)b * O + o) * H + (h0 + r)) * W + w0 + colbase]) = v;
    }
}

// ---------------------------------------------------------------------------
extern "C" void kernel_launch(void* const* d_in, const int* in_sizes, int n_in,
                              void* d_out, int out_size) {
    const float* x = (const float*)d_in[0];   // [16,512,64,64]
    const float* s = (const float*)d_in[1];   // [16,512]
    const float* w = (const float*)d_in[2];   // [512,512,3,3]
    float* out = (float*)d_out;               // [16,512,64,64]

    (void)in_sizes; (void)n_in; (void)out_size;

    wsq_kernel<<<(O * C + 255) / 256, 256>>>(w);
    siginv_kernel<<<(B * O) / 8, 256>>>(s);

    dim3 grid(16, O / OT, B);   // spatial, o-tiles, batch (batch slowest)
    conv_kernel<<<grid, 256>>>(x, s, w, out);
}

// round 2
// speedup vs baseline: 2.7361x; 2.7361x over previous
#include <cuda_runtime.h>
#include <cstdint>

// ConvModLayer via tap-decomposed implicit GEMM on tensor cores (tf32 mma.sync).
// out[b,o] = siginv[b,o] * sum_{tap,i} (c*W[o,i,tap]) * (x[b,i]*s[b,i]) shifted
// siginv[b,o] = rsqrt(c^2 * sum_i s[b,i]^2 * wsq[o,i] + 1e-8)

#define NB 16
#define NC 512
#define NO 512
#define NH 64
#define NW 64

#define XP 66              // padded spatial dim
#define WS_STRIDE 12       // smem weight inner stride (bank-conflict-free)
#define XT_STRIDE 68       // smem x row stride (bank-conflict-free)

// scratch (static device allocations are allowed)
__device__ float g_wsq[NO * NC];                 // sum_t W^2
__device__ float g_siginv[NB * NO];              // demodulation
__device__ float g_xpad[(size_t)NB * NC * XP * XP];   // x*s, zero halo, tf32-rounded (~143MB)
__device__ float g_wt[9 * NO * NC];              // [tap][o][i], c folded, tf32-rounded

__device__ __forceinline__ float tf32r(float f) {
    uint32_t u;
    asm("cvt.rna.tf32.f32 %0, %1;" : "=r"(u) : "f"(f));
    return __uint_as_float(u);
}

// ---------------------------------------------------------------------------
__global__ void wsq_kernel(const float* __restrict__ w) {
    int idx = blockIdx.x * blockDim.x + threadIdx.x;   // o*512 + i
    if (idx >= NO * NC) return;
    const float* p = w + (size_t)idx * 9;
    float sum = 0.f;
#pragma unroll
    for (int t = 0; t < 9; t++) { float v = p[t]; sum += v * v; }
    g_wsq[idx] = sum;
}

__global__ void siginv_kernel(const float* __restrict__ s) {
    int gw = blockIdx.x * (blockDim.x >> 5) + (threadIdx.x >> 5); // b*512+o
    if (gw >= NB * NO) return;
    int b = gw >> 9, o = gw & 511, lane = threadIdx.x & 31;
    float sum = 0.f;
    for (int i = lane; i < NC; i += 32) {
        float sv = s[b * NC + i];
        sum += sv * sv * g_wsq[o * NC + i];
    }
#pragma unroll
    for (int off = 16; off > 0; off >>= 1)
        sum += __shfl_xor_sync(0xFFFFFFFFu, sum, off);
    if (lane == 0) {
        const float c2 = 1.0f / (float)(NC * 9);
        g_siginv[gw] = rsqrtf(sum * c2 + 1e-8f);
    }
}

// xpad[b][ch][r][c] = (interior) ? tf32(x[b][ch][r-1][c-1] * s[b][ch]) : 0
__global__ void xpad_kernel(const float* __restrict__ x, const float* __restrict__ s) {
    size_t idx = (size_t)blockIdx.x * blockDim.x + threadIdx.x;
    const size_t total = (size_t)NB * NC * XP * XP;
    if (idx >= total) return;
    int p  = (int)(idx % (XP * XP));
    int bc = (int)(idx / (XP * XP));      // b*512 + ch
    int r = p / XP, c = p % XP;
    float v = 0.f;
    if (r >= 1 && r <= NH && c >= 1 && c <= NW)
        v = x[((size_t)bc * NH + (r - 1)) * NW + (c - 1)] * __ldg(&s[bc]);
    g_xpad[idx] = tf32r(v);
}

// wt[tap][o][i] = tf32(c * w[o][i][tap])
__global__ void wt_kernel(const float* __restrict__ w) {
    int idx = blockIdx.x * blockDim.x + threadIdx.x;
    if (idx >= 9 * NO * NC) return;
    int tap = idx >> 18;             // / (512*512)
    int o   = (idx >> 9) & 511;
    int i   = idx & 511;
    const float cc = rsqrtf((float)(NC * 9));
    g_wt[idx] = tf32r(w[((size_t)o * NC + i) * 9 + tap] * cc);
}

// ---------------------------------------------------------------------------
// Conv mainloop. CTA: 128 o x 256 px (4 image rows). 256 threads, 8 warps.
// warp = (wm 0..1)*(wn 0..3): 64 o x 64 px (one image row) per warp.
// Per warp: 4 m-tiles (m16) x 8 n-tiles (n8), mma.m16n8k8.tf32.
// ---------------------------------------------------------------------------
#define SMEM_WS_ELEMS (9 * 128 * WS_STRIDE)        // 13824
#define SMEM_XT_ELEMS (8 * 6 * XT_STRIDE)          // 3264
#define SMEM_BYTES    ((SMEM_WS_ELEMS + SMEM_XT_ELEMS) * 4)

__device__ __forceinline__ void mma_tf32(float d[4],
                                         uint32_t a0, uint32_t a1, uint32_t a2, uint32_t a3,
                                         uint32_t b0, uint32_t b1) {
    asm volatile(
        "mma.sync.aligned.m16n8k8.row.col.f32.tf32.tf32.f32 "
        "{%0,%1,%2,%3}, {%4,%5,%6,%7}, {%8,%9}, {%0,%1,%2,%3};\n"
        : "+f"(d[0]), "+f"(d[1]), "+f"(d[2]), "+f"(d[3])
        : "r"(a0), "r"(a1), "r"(a2), "r"(a3), "r"(b0), "r"(b1));
}

__global__ void __launch_bounds__(256, 1)
conv_mma_kernel(float* __restrict__ out) {
    extern __shared__ float smem[];
    float* ws = smem;                    // [tap(9)][o(128)][WS_STRIDE]
    float* xt = smem + SMEM_WS_ELEMS;    // [ch(8)][row(6)][XT_STRIDE]

    const int b  = blockIdx.z;
    const int ob = blockIdx.y * 128;
    const int h0 = blockIdx.x * 4;

    const int tid  = threadIdx.x;
    const int lane = tid & 31;
    const int warp = tid >> 5;
    const int wm = warp >> 2;            // 0..1  (o 64-chunk)
    const int wn = warp & 3;             // 0..3  (image row within tile)
    const int gid = lane >> 2;           // groupID
    const int tg  = lane & 3;            // threadID in group

    float acc[4][8][4];
#pragma unroll
    for (int mt = 0; mt < 4; mt++)
#pragma unroll
        for (int nt = 0; nt < 8; nt++)
#pragma unroll
            for (int q = 0; q < 4; q++) acc[mt][nt][q] = 0.f;

    for (int ic0 = 0; ic0 < NC; ic0 += 8) {
        __syncthreads();
        // weights: 9 taps x 128 o x 8 i = 9216 elems
        for (int e = tid; e < 9216; e += 256) {
            int tap = e >> 10;
            int rem = e & 1023;
            int o = rem >> 3, k = rem & 7;
            ws[(tap * 128 + o) * WS_STRIDE + k] =
                g_wt[((size_t)(tap * NO + ob + o)) * NC + ic0 + k];
        }
        // x tile: 8 ch x 6 rows x 66 cols = 3168 elems (xpad rows h0..h0+5)
        for (int e = tid; e < 3168; e += 256) {
            int ch  = e / 396;
            int rem = e - ch * 396;
            int row = rem / 66;
            int col = rem - row * 66;
            xt[(ch * 6 + row) * XT_STRIDE + col] =
                g_xpad[(((size_t)(b * NC + ic0 + ch)) * XP + h0 + row) * XP + col];
        }
        __syncthreads();

#pragma unroll
        for (int dh = 0; dh < 3; dh++) {
#pragma unroll
            for (int dw = 0; dw < 3; dw++) {
                const int tap = dh * 3 + dw;
                uint32_t a[4][4];
#pragma unroll
                for (int mt = 0; mt < 4; mt++) {
                    const float* p = &ws[(tap * 128 + wm * 64 + mt * 16 + gid) * WS_STRIDE];
                    a[mt][0] = __float_as_uint(p[tg]);
                    a[mt][1] = __float_as_uint(p[8 * WS_STRIDE + tg]);
                    a[mt][2] = __float_as_uint(p[tg + 4]);
                    a[mt][3] = __float_as_uint(p[8 * WS_STRIDE + tg + 4]);
                }
                const float* xr0 = &xt[(tg * 6 + wn + dh) * XT_STRIDE + dw];
                const float* xr1 = &xt[((tg + 4) * 6 + wn + dh) * XT_STRIDE + dw];
#pragma unroll
                for (int nt = 0; nt < 8; nt++) {
                    const int pc = nt * 8 + gid;
                    uint32_t b0 = __float_as_uint(xr0[pc]);
                    uint32_t b1 = __float_as_uint(xr1[pc]);
#pragma unroll
                    for (int mt = 0; mt < 4; mt++)
                        mma_tf32(acc[mt][nt], a[mt][0], a[mt][1], a[mt][2], a[mt][3], b0, b1);
                }
            }
        }
    }

    // epilogue: scale by siginv, write float2 pairs
    const int h = h0 + wn;
#pragma unroll
    for (int mt = 0; mt < 4; mt++) {
        const int o0 = ob + wm * 64 + mt * 16 + gid;
        const float s0 = g_siginv[b * NO + o0];
        const float s1 = g_siginv[b * NO + o0 + 8];
#pragma unroll
        for (int nt = 0; nt < 8; nt++) {
            const int col = nt * 8 + tg * 2;
            float2 v0 = make_float2(acc[mt][nt][0] * s0, acc[mt][nt][1] * s0);
            float2 v1 = make_float2(acc[mt][nt][2] * s1, acc[mt][nt][3] * s1);
            *reinterpret_cast<float2*>(
                &out[(((size_t)b * NO + o0) * NH + h) * NW + col]) = v0;
            *reinterpret_cast<float2*>(
                &out[(((size_t)b * NO + o0 + 8) * NH + h) * NW + col]) = v1;
        }
    }
}

// ---------------------------------------------------------------------------
extern "C" void kernel_launch(void* const* d_in, const int* in_sizes, int n_in,
                              void* d_out, int out_size) {
    const float* x = (const float*)d_in[0];   // [16,512,64,64]
    const float* s = (const float*)d_in[1];   // [16,512]
    const float* w = (const float*)d_in[2];   // [512,512,3,3]
    float* out = (float*)d_out;
    (void)in_sizes; (void)n_in; (void)out_size;

    wsq_kernel<<<(NO * NC + 255) / 256, 256>>>(w);
    siginv_kernel<<<(NB * NO) / 8, 256>>>(s);

    const size_t xtot = (size_t)NB * NC * XP * XP;
    xpad_kernel<<<(unsigned)((xtot + 255) / 256), 256>>>(x, s);
    wt_kernel<<<(9 * NO * NC + 255) / 256, 256>>>(w);

    cudaFuncSetAttribute(conv_mma_kernel,
                         cudaFuncAttributeMaxDynamicSharedMemorySize, SMEM_BYTES);
    dim3 grid(NH / 4, NO / 128, NB);   // 16 x 4 x 16 = 1024 CTAs
    conv_mma_kernel<<<grid, 256, SMEM_BYTES>>>(out);
}

// round 3
// speedup vs baseline: 2.7530x; 1.0061x over previous
#include <cuda_runtime.h>
#include <cstdint>

// ConvModLayer via tap-decomposed implicit GEMM on tensor cores (tf32 mma.sync).
// out[b,o] = siginv[b,o] * sum_{tap,i} (c*W[o,i,tap]) * (x[b,i]*s[b,i]) shifted
// siginv[b,o] = rsqrt(c^2 * sum_i s[b,i]^2 * wsq[o,i] + 1e-8)

#define NB 16
#define NC 512
#define NO 512
#define NH 64
#define NW 64

#define XP 66              // padded spatial dim
#define WS_STRIDE 12       // smem weight inner stride (bank-conflict-free)
#define XT_STRIDE 68       // smem x row stride (bank-conflict-free)

// scratch (static device allocations are allowed)
__device__ float g_wsq[NO * NC];                 // sum_t W^2
__device__ float g_siginv[NB * NO];              // demodulation
__device__ float g_xpad[(size_t)NB * NC * XP * XP];   // x*s, zero halo, tf32-rounded (~143MB)
__device__ float g_wt[9 * NO * NC];              // [tap][o][i], c folded, tf32-rounded

__device__ __forceinline__ float tf32r(float f) {
    uint32_t u;
    asm("cvt.rna.tf32.f32 %0, %1;" : "=r"(u) : "f"(f));
    return __uint_as_float(u);
}

// ---------------------------------------------------------------------------
__global__ void wsq_kernel(const float* __restrict__ w) {
    int idx = blockIdx.x * blockDim.x + threadIdx.x;   // o*512 + i
    if (idx >= NO * NC) return;
    const float* p = w + (size_t)idx * 9;
    float sum = 0.f;
#pragma unroll
    for (int t = 0; t < 9; t++) { float v = p[t]; sum += v * v; }
    g_wsq[idx] = sum;
}

__global__ void siginv_kernel(const float* __restrict__ s) {
    int gw = blockIdx.x * (blockDim.x >> 5) + (threadIdx.x >> 5); // b*512+o
    if (gw >= NB * NO) return;
    int b = gw >> 9, o = gw & 511, lane = threadIdx.x & 31;
    float sum = 0.f;
    for (int i = lane; i < NC; i += 32) {
        float sv = s[b * NC + i];
        sum += sv * sv * g_wsq[o * NC + i];
    }
#pragma unroll
    for (int off = 16; off > 0; off >>= 1)
        sum += __shfl_xor_sync(0xFFFFFFFFu, sum, off);
    if (lane == 0) {
        const float c2 = 1.0f / (float)(NC * 9);
        g_siginv[gw] = rsqrtf(sum * c2 + 1e-8f);
    }
}

// xpad[b][ch][r][c] = (interior) ? tf32(x[b][ch][r-1][c-1] * s[b][ch]) : 0
__global__ void xpad_kernel(const float* __restrict__ x, const float* __restrict__ s) {
    size_t idx = (size_t)blockIdx.x * blockDim.x + threadIdx.x;
    const size_t total = (size_t)NB * NC * XP * XP;
    if (idx >= total) return;
    int p  = (int)(idx % (XP * XP));
    int bc = (int)(idx / (XP * XP));      // b*512 + ch
    int r = p / XP, c = p % XP;
    float v = 0.f;
    if (r >= 1 && r <= NH && c >= 1 && c <= NW)
        v = x[((size_t)bc * NH + (r - 1)) * NW + (c - 1)] * __ldg(&s[bc]);
    g_xpad[idx] = tf32r(v);
}

// wt[tap][o][i] = tf32(c * w[o][i][tap])
__global__ void wt_kernel(const float* __restrict__ w) {
    int idx = blockIdx.x * blockDim.x + threadIdx.x;
    if (idx >= 9 * NO * NC) return;
    int tap = idx >> 18;             // / (512*512)
    int o   = (idx >> 9) & 511;
    int i   = idx & 511;
    const float cc = rsqrtf((float)(NC * 9));
    g_wt[idx] = tf32r(w[((size_t)o * NC + i) * 9 + tap] * cc);
}

// ---------------------------------------------------------------------------
// Conv mainloop. CTA: 128 o x 256 px (4 image rows). 256 threads, 8 warps.
// warp = (wm 0..1)*(wn 0..3): 64 o x 64 px (one image row) per warp.
// Per warp: 4 m-tiles (m16) x 8 n-tiles (n8), mma.m16n8k8.tf32.
// ---------------------------------------------------------------------------
#define SMEM_WS_ELEMS (9 * 128 * WS_STRIDE)        // 13824
#define SMEM_XT_ELEMS (8 * 6 * XT_STRIDE)          // 3264
#define SMEM_BYTES    ((SMEM_WS_ELEMS + SMEM_XT_ELEMS) * 4)

__device__ __forceinline__ void mma_tf32(float d[4],
                                         uint32_t a0, uint32_t a1, uint32_t a2, uint32_t a3,
                                         uint32_t b0, uint32_t b1) {
    asm volatile(
        "mma.sync.aligned.m16n8k8.row.col.f32.tf32.tf32.f32 "
        "{%0,%1,%2,%3}, {%4,%5,%6,%7}, {%8,%9}, {%0,%1,%2,%3};\n"
        : "+f"(d[0]), "+f"(d[1]), "+f"(d[2]), "+f"(d[3])
        : "r"(a0), "r"(a1), "r"(a2), "r"(a3), "r"(b0), "r"(b1));
}

__global__ void __launch_bounds__(256, 1)
conv_mma_kernel(float* __restrict__ out) {
    extern __shared__ float smem[];
    float* ws = smem;                    // [tap(9)][o(128)][WS_STRIDE]
    float* xt = smem + SMEM_WS_ELEMS;    // [ch(8)][row(6)][XT_STRIDE]

    const int b  = blockIdx.z;
    const int ob = blockIdx.y * 128;
    const int h0 = blockIdx.x * 4;

    const int tid  = threadIdx.x;
    const int lane = tid & 31;
    const int warp = tid >> 5;
    const int wm = warp >> 2;            // 0..1  (o 64-chunk)
    const int wn = warp & 3;             // 0..3  (image row within tile)
    const int gid = lane >> 2;           // groupID
    const int tg  = lane & 3;            // threadID in group

    float acc[4][8][4];
#pragma unroll
    for (int mt = 0; mt < 4; mt++)
#pragma unroll
        for (int nt = 0; nt < 8; nt++)
#pragma unroll
            for (int q = 0; q < 4; q++) acc[mt][nt][q] = 0.f;

    for (int ic0 = 0; ic0 < NC; ic0 += 8) {
        __syncthreads();
        // weights: 9 taps x 128 o x 8 i = 9216 elems
        for (int e = tid; e < 9216; e += 256) {
            int tap = e >> 10;
            int rem = e & 1023;
            int o = rem >> 3, k = rem & 7;
            ws[(tap * 128 + o) * WS_STRIDE + k] =
                g_wt[((size_t)(tap * NO + ob + o)) * NC + ic0 + k];
        }
        // x tile: 8 ch x 6 rows x 66 cols = 3168 elems (xpad rows h0..h0+5)
        for (int e = tid; e < 3168; e += 256) {
            int ch  = e / 396;
            int rem = e - ch * 396;
            int row = rem / 66;
            int col = rem - row * 66;
            xt[(ch * 6 + row) * XT_STRIDE + col] =
                g_xpad[(((size_t)(b * NC + ic0 + ch)) * XP + h0 + row) * XP + col];
        }
        __syncthreads();

#pragma unroll
        for (int dh = 0; dh < 3; dh++) {
#pragma unroll
            for (int dw = 0; dw < 3; dw++) {
                const int tap = dh * 3 + dw;
                uint32_t a[4][4];
#pragma unroll
                for (int mt = 0; mt < 4; mt++) {
                    const float* p = &ws[(tap * 128 + wm * 64 + mt * 16 + gid) * WS_STRIDE];
                    a[mt][0] = __float_as_uint(p[tg]);
                    a[mt][1] = __float_as_uint(p[8 * WS_STRIDE + tg]);
                    a[mt][2] = __float_as_uint(p[tg + 4]);
                    a[mt][3] = __float_as_uint(p[8 * WS_STRIDE + tg + 4]);
                }
                const float* xr0 = &xt[(tg * 6 + wn + dh) * XT_STRIDE + dw];
                const float* xr1 = &xt[((tg + 4) * 6 + wn + dh) * XT_STRIDE + dw];
#pragma unroll
                for (int nt = 0; nt < 8; nt++) {
                    const int pc = nt * 8 + gid;
                    uint32_t b0 = __float_as_uint(xr0[pc]);
                    uint32_t b1 = __float_as_uint(xr1[pc]);
#pragma unroll
                    for (int mt = 0; mt < 4; mt++)
                        mma_tf32(acc[mt][nt], a[mt][0], a[mt][1], a[mt][2], a[mt][3], b0, b1);
                }
            }
        }
    }

    // epilogue: scale by siginv, write float2 pairs
    const int h = h0 + wn;
#pragma unroll
    for (int mt = 0; mt < 4; mt++) {
        const int o0 = ob + wm * 64 + mt * 16 + gid;
        const float s0 = g_siginv[b * NO + o0];
        const float s1 = g_siginv[b * NO + o0 + 8];
#pragma unroll
        for (int nt = 0; nt < 8; nt++) {
            const int col = nt * 8 + tg * 2;
            float2 v0 = make_float2(acc[mt][nt][0] * s0, acc[mt][nt][1] * s0);
            float2 v1 = make_float2(acc[mt][nt][2] * s1, acc[mt][nt][3] * s1);
            *reinterpret_cast<float2*>(
                &out[(((size_t)b * NO + o0) * NH + h) * NW + col]) = v0;
            *reinterpret_cast<float2*>(
                &out[(((size_t)b * NO + o0 + 8) * NH + h) * NW + col]) = v1;
        }
    }
}

// ---------------------------------------------------------------------------
extern "C" void kernel_launch(void* const* d_in, const int* in_sizes, int n_in,
                              void* d_out, int out_size) {
    const float* x = (const float*)d_in[0];   // [16,512,64,64]
    const float* s = (const float*)d_in[1];   // [16,512]
    const float* w = (const float*)d_in[2];   // [512,512,3,3]
    float* out = (float*)d_out;
    (void)in_sizes; (void)n_in; (void)out_size;

    wsq_kernel<<<(NO * NC + 255) / 256, 256>>>(w);
    siginv_kernel<<<(NB * NO) / 8, 256>>>(s);

    const size_t xtot = (size_t)NB * NC * XP * XP;
    xpad_kernel<<<(unsigned)((xtot + 255) / 256), 256>>>(x, s);
    wt_kernel<<<(9 * NO * NC + 255) / 256, 256>>>(w);

    cudaFuncSetAttribute(conv_mma_kernel,
                         cudaFuncAttributeMaxDynamicSharedMemorySize, SMEM_BYTES);
    dim3 grid(NH / 4, NO / 128, NB);   // 16 x 4 x 16 = 1024 CTAs
    conv_mma_kernel<<<grid, 256, SMEM_BYTES>>>(out);
}

// round 5
// speedup vs baseline: 8.5742x; 3.1145x over previous
#include <cuda_runtime.h>
#include <cuda_fp16.h>
#include <cstdint>

#define NB 16
#define NC 512
#define NO 512
#define NH 64
#define NW 64

__device__ float g_wsq[NO * NC];
__device__ float g_siginv[NB * NO];
__device__ __half g_wh[9 * NO * NC];                   // [tap][o][i], c folded
__device__ __half g_xhh[(size_t)NB * 66 * 72 * 512];   // [b][row][px][ch], x*s, halo=0

// ---------------- prepass ----------------
__global__ void wsq_kernel(const float* __restrict__ w) {
    int idx = blockIdx.x * blockDim.x + threadIdx.x;
    if (idx >= NO * NC) return;
    const float* p = w + (size_t)idx * 9;
    float sum = 0.f;
#pragma unroll
    for (int t = 0; t < 9; t++) { float v = p[t]; sum += v * v; }
    g_wsq[idx] = sum;
}
__global__ void siginv_kernel(const float* __restrict__ s) {
    int gw = blockIdx.x * (blockDim.x >> 5) + (threadIdx.x >> 5);
    if (gw >= NB * NO) return;
    int b = gw >> 9, o = gw & 511, lane = threadIdx.x & 31;
    float sum = 0.f;
    for (int i = lane; i < NC; i += 32) {
        float sv = s[b * NC + i];
        sum += sv * sv * g_wsq[o * NC + i];
    }
#pragma unroll
    for (int off = 16; off > 0; off >>= 1)
        sum += __shfl_xor_sync(0xFFFFFFFFu, sum, off);
    if (lane == 0) g_siginv[gw] = rsqrtf(sum * (1.0f / (NC * 9)) + 1e-8f);
}
__global__ void wh_kernel(const float* __restrict__ w) {
    int idx = blockIdx.x * blockDim.x + threadIdx.x;
    if (idx >= 9 * NO * NC) return;
    int tap = idx >> 18, o = (idx >> 9) & 511, i = idx & 511;
    g_wh[idx] = __float2half(w[((size_t)o * NC + i) * 9 + tap] * rsqrtf((float)(NC * 9)));
}
__global__ void xhh_kernel(const float* __restrict__ x, const float* __restrict__ s) {
    const int r = blockIdx.x, b = blockIdx.y, tid = threadIdx.x;
    __half* dst = g_xhh + ((size_t)(b * 66 + r)) * 72 * 512;
    const int xrow = r - 1;
    if (xrow < 0 || xrow >= NH) {
        for (int e = tid; e < 72 * 512; e += 256) dst[e] = __float2half(0.f);
        return;
    }
    for (int e = tid; e < 8 * 512; e += 256) {      // zero px 0 and 65..71
        int pp = e >> 9, ch = e & 511;
        int p = (pp == 0) ? 0 : 64 + pp;
        dst[p * 512 + ch] = __float2half(0.f);
    }
    __shared__ float tile[32][65];
    for (int cb = 0; cb < 16; cb++) {
        __syncthreads();
        for (int e = tid; e < 32 * 64; e += 256) {
            int cc = e >> 6, px = e & 63;
            tile[cc][px] = x[(((size_t)b * 512 + cb * 32 + cc) * NH + xrow) * NW + px];
        }
        __syncthreads();
        for (int e = tid; e < 64 * 32; e += 256) {
            int px = e >> 5, cc = e & 31, ch = cb * 32 + cc;
            dst[(px + 1) * 512 + ch] = __float2half(tile[cc][px] * __ldg(&s[b * 512 + ch]));
        }
    }
}

// ---------------- main conv: fp16 mma + ldmatrix + cp.async ----------------
#define APITCH 24                       // halves per A row (48B, conflict-free ldmatrix)
#define BPITCH 24
#define ASZ (9 * 128 * APITCH)          // halves per A buffer
#define BSZ (6 * 72 * BPITCH)
#define SMEM_BYTES ((2 * ASZ + 2 * BSZ) * 2)

#define CP16(dst, src) \
    asm volatile("cp.async.cg.shared.global [%0], [%1], 16;" :: "r"(dst), "l"(src))
#define CP_COMMIT() asm volatile("cp.async.commit_group;" ::: "memory")
#define LDMX4(r, a) asm volatile( \
    "ldmatrix.sync.aligned.m8n8.x4.shared.b16 {%0,%1,%2,%3}, [%4];" \
    : "=r"((r)[0]), "=r"((r)[1]), "=r"((r)[2]), "=r"((r)[3]) : "r"(a))
#define LDMX2(r0, r1, a) asm volatile( \
    "ldmatrix.sync.aligned.m8n8.x2.shared.b16 {%0,%1}, [%2];" \
    : "=r"(r0), "=r"(r1) : "r"(a))

__device__ __forceinline__ void mma_fp16(float d[4], const uint32_t a[4],
                                         uint32_t b0, uint32_t b1) {
    asm volatile(
        "mma.sync.aligned.m16n8k16.row.col.f32.f16.f16.f32 "
        "{%0,%1,%2,%3}, {%4,%5,%6,%7}, {%8,%9}, {%0,%1,%2,%3};\n"
        : "+f"(d[0]), "+f"(d[1]), "+f"(d[2]), "+f"(d[3])
        : "r"(a[0]), "r"(a[1]), "r"(a[2]), "r"(a[3]), "r"(b0), "r"(b1));
}

__global__ void __launch_bounds__(256, 1)
conv_fp16_kernel(float* __restrict__ out) {
    extern __shared__ __half sm[];
    const int b  = blockIdx.z;
    const int ob = blockIdx.y * 128;
    const int h0 = blockIdx.x * 4;

    const int tid  = threadIdx.x;
    const int lane = tid & 31;
    const int warp = tid >> 5;
    const int wm = warp >> 2, wn = warp & 3;
    const int gid = lane >> 3 ? 0 : 0;   // placeholder (unused)
    const int g4  = lane >> 2;           // groupID (0..7)
    const int tg  = lane & 3;

    uint32_t smbase;
    asm("{ .reg .u64 t; cvta.to.shared.u64 t, %1; cvt.u32.u64 %0, t; }"
        : "=r"(smbase) : "l"((const void*)sm));
    const uint32_t A0 = smbase;                  // A bufs: [2][ASZ]
    const uint32_t B0 = smbase + 2 * ASZ * 2;    // B bufs: [2][BSZ]

    // ldmatrix lane-addressing components
    const int lg = lane >> 3, lr = lane & 7;
    // A: row = wm*64 + mt*16 + (lg&1)*8 + lr; col = (lg>>1)*8
    const uint32_t a_lane = (uint32_t)((wm * 64 + (lg & 1) * 8 + lr) * (APITCH * 2)
                                       + (lg >> 1) * 16);
    // B: row index (wn+dh)*72 + nt*8 + lr + dw ; col = ((lane>>3)&1)*8
    const uint32_t b_lane = (uint32_t)(lr * (BPITCH * 2) + (lg & 1) * 16);

    float acc[4][8][4];
#pragma unroll
    for (int mt = 0; mt < 4; mt++)
#pragma unroll
        for (int nt = 0; nt < 8; nt++)
#pragma unroll
            for (int q = 0; q < 4; q++) acc[mt][nt][q] = 0.f;

    const __half* wsrc = g_wh + ob * NC;
    const __half* xsrc = g_xhh + ((size_t)(b * 66 + h0)) * 72 * 512;

    auto load_chunk = [&](int c, int buf) {
        const uint32_t Ad = A0 + buf * ASZ * 2;
        const uint32_t Bd = B0 + buf * BSZ * 2;
#pragma unroll 3
        for (int e = tid; e < 2304; e += 256) {     // A: 9 tap * 128 o * 2 halves-of-16
            int tap = e >> 8, rem = e & 255, o = rem >> 1, h = rem & 1;
            CP16(Ad + (uint32_t)((tap * 128 + o) * (APITCH * 2) + h * 16),
                 wsrc + ((size_t)tap * NO + o) * NC + c * 16 + h * 8);
        }
#pragma unroll 2
        for (int e = tid; e < 864; e += 256) {      // B: 6 rows * 72 px * 2
            int row = e / 144, rem = e - row * 144, px = rem >> 1, h = rem & 1;
            CP16(Bd + (uint32_t)((row * 72 + px) * (BPITCH * 2) + h * 16),
                 xsrc + ((size_t)(row * 72 + px)) * 512 + c * 16 + h * 8);
        }
        CP_COMMIT();
    };

    load_chunk(0, 0);

    for (int c = 0; c < 32; c++) {
        const int buf = c & 1;
        if (c + 1 < 32) {
            load_chunk(c + 1, buf ^ 1);
            asm volatile("cp.async.wait_group 1;" ::: "memory");
        } else {
            asm volatile("cp.async.wait_group 0;" ::: "memory");
        }
        __syncthreads();

        const uint32_t Abuf = A0 + buf * ASZ * 2;
        const uint32_t Bbuf = B0 + buf * BSZ * 2;
#pragma unroll
        for (int dh = 0; dh < 3; dh++) {
#pragma unroll
            for (int dw = 0; dw < 3; dw++) {
                const int tap = dh * 3 + dw;
                uint32_t a[4][4];
#pragma unroll
                for (int mt = 0; mt < 4; mt++)
                    LDMX4(a[mt], Abuf + (uint32_t)((tap * 128 + mt * 16) * (APITCH * 2))
                                 + a_lane);
                const uint32_t brow = Bbuf
                    + (uint32_t)(((wn + dh) * 72 + dw) * (BPITCH * 2)) + b_lane;
#pragma unroll
                for (int nt = 0; nt < 8; nt++) {
                    uint32_t b0, b1;
                    LDMX2(b0, b1, brow + (uint32_t)(nt * 8 * (BPITCH * 2)));
#pragma unroll
                    for (int mt = 0; mt < 4; mt++)
                        mma_fp16(acc[mt][nt], a[mt], b0, b1);
                }
            }
        }
        __syncthreads();
    }

    // epilogue
    const int h = h0 + wn;
#pragma unroll
    for (int mt = 0; mt < 4; mt++) {
        const int o0 = ob + wm * 64 + mt * 16 + g4;
        const float s0 = g_siginv[b * NO + o0];
        const float s1 = g_siginv[b * NO + o0 + 8];
#pragma unroll
        for (int nt = 0; nt < 8; nt++) {
            const int col = nt * 8 + tg * 2;
            float2 v0 = make_float2(acc[mt][nt][0] * s0, acc[mt][nt][1] * s0);
            float2 v1 = make_float2(acc[mt][nt][2] * s1, acc[mt][nt][3] * s1);
            *reinterpret_cast<float2*>(
                &out[(((size_t)b * NO + o0) * NH + h) * NW + col]) = v0;
            *reinterpret_cast<float2*>(
                &out[(((size_t)b * NO + o0 + 8) * NH + h) * NW + col]) = v1;
        }
    }
}

// ---------------------------------------------------------------------------
extern "C" void kernel_launch(void* const* d_in, const int* in_sizes, int n_in,
                              void* d_out, int out_size) {
    const float* x = (const float*)d_in[0];
    const float* s = (const float*)d_in[1];
    const float* w = (const float*)d_in[2];
    float* out = (float*)d_out;
    (void)in_sizes; (void)n_in; (void)out_size;

    wsq_kernel<<<(NO * NC + 255) / 256, 256>>>(w);
    siginv_kernel<<<(NB * NO) / 8, 256>>>(s);
    wh_kernel<<<(9 * NO * NC + 255) / 256, 256>>>(w);
    dim3 xg(66, NB);
    xhh_kernel<<<xg, 256>>>(x, s);

    cudaFuncSetAttribute(conv_fp16_kernel,
                         cudaFuncAttributeMaxDynamicSharedMemorySize, SMEM_BYTES);
    dim3 grid(16, NO / 128, NB);
    conv_fp16_kernel<<<grid, 256, SMEM_BYTES>>>(out);
}